// round 13
// baseline (speedup 1.0000x reference)
#include <cuda_runtime.h>
#include <cuda_fp16.h>
#include <cstdint>

#define E_ 8
#define H_ 1024
#define I_ 2048
#define T_ 1024

// stage layout (bytes): A 64x80 | B 128x80
#define ATILE 5120
#define STGB  15360
#define NSTG  4
#define SMEMSZ (NSTG * STGB)          // 61440 B per CTA -> 3 CTA/SM

// ---------------- scratch ----------------
__device__ int   g_cnt[E_];
__device__ int   g_tok[E_ * T_];
__device__ int   g_slot[E_ * T_];
__device__ float g_gate[E_ * T_];
__device__ __half g_xh[T_ * H_];
__device__ __half g_acth[(size_t)E_ * T_ * I_];
__device__ float g_ypart[(size_t)T_ * 2 * H_];

// ---------------- helpers ----------------
__device__ __forceinline__ void cp16(uint32_t sa, const void* g) {
    asm volatile("cp.async.cg.shared.global [%0], [%1], 16;\n" :: "r"(sa), "l"(g));
}
__device__ __forceinline__ void cp_commit() { asm volatile("cp.async.commit_group;\n"); }
__device__ __forceinline__ void cp_wait2()  { asm volatile("cp.async.wait_group 2;\n"); }

__device__ __forceinline__ uint32_t pack_h2(float lo, float hi) {
    uint32_t r;
    asm("cvt.rn.f16x2.f32 %0, %1, %2;" : "=r"(r) : "f"(hi), "f"(lo));
    return r;
}
__device__ __forceinline__ void ldsm4(uint32_t r[4], uint32_t a) {
    asm volatile("ldmatrix.sync.aligned.m8n8.x4.shared.b16 {%0,%1,%2,%3}, [%4];"
        : "=r"(r[0]), "=r"(r[1]), "=r"(r[2]), "=r"(r[3]) : "r"(a));
}
__device__ __forceinline__ void hmma(float c[4], const uint32_t a[4], uint32_t b0, uint32_t b1) {
    asm volatile(
        "mma.sync.aligned.m16n8k16.row.col.f32.f16.f16.f32 "
        "{%0,%1,%2,%3}, {%4,%5,%6,%7}, {%8,%9}, {%0,%1,%2,%3};\n"
        : "+f"(c[0]), "+f"(c[1]), "+f"(c[2]), "+f"(c[3])
        : "r"(a[0]), "r"(a[1]), "r"(a[2]), "r"(a[3]), "r"(b0), "r"(b1));
}
__device__ __forceinline__ void sts128(uint32_t a, uint32_t u0, uint32_t u1, uint32_t u2, uint32_t u3) {
    asm volatile("st.shared.v4.b32 [%0], {%1,%2,%3,%4};"
        :: "r"(a), "r"(u0), "r"(u1), "r"(u2), "r"(u3));
}

// ---------------- small kernels ----------------
__global__ void zero_cnt_kernel() { if (threadIdx.x < E_) g_cnt[threadIdx.x] = 0; }

__global__ void presplit_kernel(const float* __restrict__ x) {
    int i = blockIdx.x * blockDim.x + threadIdx.x;    // over T_*H_/4
    float4 v = reinterpret_cast<const float4*>(x)[i];
    reinterpret_cast<uint2*>(g_xh)[i] = make_uint2(pack_h2(v.x, v.y), pack_h2(v.z, v.w));
}

__global__ void router_kernel(const float* __restrict__ logits) {
    int t = blockIdx.x * blockDim.x + threadIdx.x;
    if (t >= T_) return;
    float l[E_]; float mx = -1e30f;
#pragma unroll
    for (int e = 0; e < E_; e++) { l[e] = logits[t * E_ + e]; mx = fmaxf(mx, l[e]); }
    float p[E_];
#pragma unroll
    for (int e = 0; e < E_; e++) p[e] = __expf(l[e] - mx);
    int i1 = 0, i2 = -1; float v1 = p[0], v2 = -1.0f;
#pragma unroll
    for (int e = 1; e < E_; e++) {
        float pe = p[e];
        if (pe > v1) { v2 = v1; i2 = i1; v1 = pe; i1 = e; }
        else if (pe > v2) { v2 = pe; i2 = e; }
    }
    float inv = 1.0f / (v1 + v2);
    int pos1 = atomicAdd(&g_cnt[i1], 1);
    g_tok[i1 * T_ + pos1] = t; g_slot[i1 * T_ + pos1] = 0; g_gate[i1 * T_ + pos1] = v1 * inv;
    int pos2 = atomicAdd(&g_cnt[i2], 1);
    g_tok[i2 * T_ + pos2] = t; g_slot[i2 * T_ + pos2] = 1; g_gate[i2 * T_ + pos2] = v2 * inv;
}

// =============== GEMM1: 64m x (64G | 64L), fp16, in-loop f32->f16 B conversion ===============
__global__ void __launch_bounds__(128, 3) gemm1_kernel(
    const float* __restrict__ w13, const float* __restrict__ b13)
{
    int e = blockIdx.z;
    int cnt = g_cnt[e];
    int m0 = blockIdx.y * 64;
    if (m0 >= cnt) return;
    int n0 = blockIdx.x * 64;
    int tid = threadIdx.x;

    extern __shared__ char smem[];
    uint32_t sb = (uint32_t)__cvta_generic_to_shared(smem);

    // ---- fill setup: lr = row (0..63), lh = half (16 floats / 32 f16-bytes) ----
    int lr = tid >> 1, lh = tid & 1;
    int mg = m0 + lr; if (mg >= cnt) mg = cnt - 1;
    const __half* ax = g_xh + (size_t)g_tok[e * T_ + mg] * H_ + lh * 16;
    const float* bgf = w13 + ((size_t)e * 2 * I_ + n0 + lr) * H_ + lh * 16;
    const float* blf = bgf + (size_t)I_ * H_;
    uint32_t adst = sb + lr * 80 + lh * 32;
    uint32_t bdst = sb + ATILE + lr * 80 + lh * 32;   // G rows; L rows at +5120

    float4 g0, g1, g2, g3, l0, l1, l2, l3;
#define LDGB1(c) {                                                       \
        const float4* pg_ = reinterpret_cast<const float4*>(bgf + (size_t)(c) * 32); \
        const float4* pl_ = reinterpret_cast<const float4*>(blf + (size_t)(c) * 32); \
        g0 = __ldg(pg_); g1 = __ldg(pg_ + 1); g2 = __ldg(pg_ + 2); g3 = __ldg(pg_ + 3); \
        l0 = __ldg(pl_); l1 = __ldg(pl_ + 1); l2 = __ldg(pl_ + 2); l3 = __ldg(pl_ + 3); }
#define STSB1(s) {                                                       \
        uint32_t o_ = bdst + (s) * STGB;                                 \
        sts128(o_,      pack_h2(g0.x,g0.y), pack_h2(g0.z,g0.w), pack_h2(g1.x,g1.y), pack_h2(g1.z,g1.w)); \
        sts128(o_ + 16, pack_h2(g2.x,g2.y), pack_h2(g2.z,g2.w), pack_h2(g3.x,g3.y), pack_h2(g3.z,g3.w)); \
        sts128(o_ + 5120,      pack_h2(l0.x,l0.y), pack_h2(l0.z,l0.w), pack_h2(l1.x,l1.y), pack_h2(l1.z,l1.w)); \
        sts128(o_ + 5120 + 16, pack_h2(l2.x,l2.y), pack_h2(l2.z,l2.w), pack_h2(l3.x,l3.y), pack_h2(l3.z,l3.w)); }
#define FILLA1(c, s) {                                                   \
        uint32_t o_ = (s) * STGB;                                        \
        cp16(adst + o_, ax + (c) * 32); cp16(adst + o_ + 16, ax + (c) * 32 + 8); \
        cp_commit(); }

    // ---- compute setup: 4 warps = 2m x 2n; warp 32m x (32G + 32L) ----
    int lane = tid & 31, warp = tid >> 5;
    int wm = warp & 1, wn = warp >> 1;
    int gid = lane >> 2, tig = lane & 3;

    uint32_t aA = sb + (wm * 32 + (lane & 15)) * 80 + (lane >> 4) * 16;
    int brl = ((lane >> 4) & 1) * 8 + (lane & 7);
    int bko = ((lane >> 3) & 1) * 16;
    uint32_t bB = sb + ATILE + bko;
    uint32_t tG0 = bB + (wn * 32 + brl) * 80;
    uint32_t tG1 = tG0 + 16 * 80;
    uint32_t tL0 = tG0 + 64 * 80;
    uint32_t tL1 = tG1 + 64 * 80;

    uint32_t bG[2][4], bL[2][4], af[2][4];
    float accG[2][4][4], accL[2][4][4];
#pragma unroll
    for (int i = 0; i < 2; i++)
#pragma unroll
        for (int j = 0; j < 4; j++)
#pragma unroll
            for (int k = 0; k < 4; k++) { accG[i][j][k] = 0.f; accL[i][j][k] = 0.f; }

#define PHASE1(ko) {                                                     \
        ldsm4(bG[0], tG0 + (ko)); ldsm4(bG[1], tG1 + (ko));              \
        ldsm4(bL[0], tL0 + (ko)); ldsm4(bL[1], tL1 + (ko));              \
        ldsm4(af[0], aA + (ko)); ldsm4(af[1], aA + (ko) + 16 * 80);      \
        _Pragma("unroll")                                                \
        for (int mi = 0; mi < 2; mi++) {                                 \
            hmma(accG[mi][0], af[mi], bG[0][0], bG[0][1]);               \
            hmma(accG[mi][1], af[mi], bG[0][2], bG[0][3]);               \
            hmma(accG[mi][2], af[mi], bG[1][0], bG[1][1]);               \
            hmma(accG[mi][3], af[mi], bG[1][2], bG[1][3]);               \
            hmma(accL[mi][0], af[mi], bL[0][0], bL[0][1]);               \
            hmma(accL[mi][1], af[mi], bL[0][2], bL[0][3]);               \
            hmma(accL[mi][2], af[mi], bL[1][0], bL[1][1]);               \
            hmma(accL[mi][3], af[mi], bL[1][2], bL[1][3]);               \
        } }

    // ---- prologue: chunks 0..2 (B converted inline, A via cp.async) ----
    LDGB1(0); STSB1(0);
    LDGB1(1); STSB1(1);
    LDGB1(2); STSB1(2);
    FILLA1(0, 0); FILLA1(1, 1); FILLA1(2, 2);

    const int NK = H_ / 32;   // 32
#pragma unroll 1
    for (int kt = 0; kt < NK; ++kt) {
        int st = kt % NSTG;
        cp_wait2();
        __syncthreads();
        int cf = kt + 3;
        bool pf = cf < NK;
        if (pf) { LDGB1(cf); FILLA1(cf, cf % NSTG); } else { cp_commit(); }
        uint32_t so = st * STGB;
        PHASE1(so);
        PHASE1(so + 32);
        if (pf) STSB1(cf % NSTG);
    }

    // ---- epilogue: bias + GLU + fp16 store ----
    float bgv[4][2], blv[4][2];
#pragma unroll
    for (int ni = 0; ni < 4; ni++) {
        int n = n0 + wn * 32 + ni * 8 + tig * 2;
        bgv[ni][0] = __ldg(&b13[(size_t)e * 2 * I_ + n]);
        bgv[ni][1] = __ldg(&b13[(size_t)e * 2 * I_ + n + 1]);
        blv[ni][0] = __ldg(&b13[(size_t)e * 2 * I_ + I_ + n]);
        blv[ni][1] = __ldg(&b13[(size_t)e * 2 * I_ + I_ + n + 1]);
    }
    size_t actbase = (size_t)e * T_ * I_;
#pragma unroll
    for (int mi = 0; mi < 2; mi++) {
#pragma unroll
        for (int rr = 0; rr < 2; rr++) {
            int m = m0 + wm * 32 + mi * 16 + gid + rr * 8;
            if (m >= cnt) continue;
            size_t rowoff = actbase + (size_t)m * I_;
#pragma unroll
            for (int ni = 0; ni < 4; ni++) {
                int n = n0 + wn * 32 + ni * 8 + tig * 2;
                float gg0 = accG[mi][ni][rr * 2 + 0] + bgv[ni][0];
                float gg1 = accG[mi][ni][rr * 2 + 1] + bgv[ni][1];
                float ll0 = accL[mi][ni][rr * 2 + 0] + blv[ni][0];
                float ll1 = accL[mi][ni][rr * 2 + 1] + blv[ni][1];
                float a0 = gg0 * (1.f / (1.f + __expf(-1.702f * gg0))) * (ll0 + 1.0f);
                float a1 = gg1 * (1.f / (1.f + __expf(-1.702f * gg1))) * (ll1 + 1.0f);
                *reinterpret_cast<uint32_t*>(g_acth + rowoff + n) = pack_h2(a0, a1);
            }
        }
    }
#undef LDGB1
#undef STSB1
#undef FILLA1
#undef PHASE1
}

// =============== GEMM2: 64m x 128n, fp16, in-loop f32->f16 B conversion ===============
__global__ void __launch_bounds__(128, 3) gemm2_kernel(
    const float* __restrict__ w2, const float* __restrict__ b2)
{
    int e = blockIdx.z;
    int cnt = g_cnt[e];
    int m0 = blockIdx.y * 64;
    if (m0 >= cnt) return;
    int n0 = blockIdx.x * 128;
    int tid = threadIdx.x;

    extern __shared__ char smem[];
    uint32_t sb = (uint32_t)__cvta_generic_to_shared(smem);

    int lr = tid >> 1, lh = tid & 1;
    int mg = m0 + lr; if (mg >= cnt) mg = cnt - 1;
    const __half* ax = g_acth + (size_t)(e * T_ + mg) * I_ + lh * 16;
    const float* b1f = w2 + (size_t)(e * H_ + n0 + lr) * I_ + lh * 16;
    const float* b2f = w2 + (size_t)(e * H_ + n0 + 64 + lr) * I_ + lh * 16;
    uint32_t adst = sb + lr * 80 + lh * 32;
    uint32_t bdst = sb + ATILE + lr * 80 + lh * 32;

    float4 g0, g1, g2, g3, l0, l1, l2, l3;
#define LDGB2(c) {                                                       \
        const float4* pg_ = reinterpret_cast<const float4*>(b1f + (size_t)(c) * 32); \
        const float4* pl_ = reinterpret_cast<const float4*>(b2f + (size_t)(c) * 32); \
        g0 = __ldg(pg_); g1 = __ldg(pg_ + 1); g2 = __ldg(pg_ + 2); g3 = __ldg(pg_ + 3); \
        l0 = __ldg(pl_); l1 = __ldg(pl_ + 1); l2 = __ldg(pl_ + 2); l3 = __ldg(pl_ + 3); }
#define STSB2(s) {                                                       \
        uint32_t o_ = bdst + (s) * STGB;                                 \
        sts128(o_,      pack_h2(g0.x,g0.y), pack_h2(g0.z,g0.w), pack_h2(g1.x,g1.y), pack_h2(g1.z,g1.w)); \
        sts128(o_ + 16, pack_h2(g2.x,g2.y), pack_h2(g2.z,g2.w), pack_h2(g3.x,g3.y), pack_h2(g3.z,g3.w)); \
        sts128(o_ + 5120,      pack_h2(l0.x,l0.y), pack_h2(l0.z,l0.w), pack_h2(l1.x,l1.y), pack_h2(l1.z,l1.w)); \
        sts128(o_ + 5120 + 16, pack_h2(l2.x,l2.y), pack_h2(l2.z,l2.w), pack_h2(l3.x,l3.y), pack_h2(l3.z,l3.w)); }
#define FILLA2(c, s) {                                                   \
        uint32_t o_ = (s) * STGB;                                        \
        cp16(adst + o_, ax + (c) * 32); cp16(adst + o_ + 16, ax + (c) * 32 + 8); \
        cp_commit(); }

    // ---- compute setup: 4 warps = 2m x 2n; warp 32m x 64n ----
    int lane = tid & 31, warp = tid >> 5;
    int wm = warp & 1, wn = warp >> 1;
    int gid = lane >> 2, tig = lane & 3;

    uint32_t aA = sb + (wm * 32 + (lane & 15)) * 80 + (lane >> 4) * 16;
    int brl = ((lane >> 4) & 1) * 8 + (lane & 7);
    int bko = ((lane >> 3) & 1) * 16;
    uint32_t bB = sb + ATILE + bko;
    uint32_t tb[4];
#pragma unroll
    for (int g = 0; g < 4; g++) tb[g] = bB + (wn * 64 + g * 16 + brl) * 80;

    uint32_t bfr[4][4], af[2][4];
    float acc[2][8][4];
#pragma unroll
    for (int i = 0; i < 2; i++)
#pragma unroll
        for (int j = 0; j < 8; j++)
#pragma unroll
            for (int k = 0; k < 4; k++) acc[i][j][k] = 0.f;

#define PHASE2(ko) {                                                     \
        _Pragma("unroll")                                                \
        for (int g = 0; g < 4; g++) ldsm4(bfr[g], tb[g] + (ko));         \
        ldsm4(af[0], aA + (ko)); ldsm4(af[1], aA + (ko) + 16 * 80);      \
        _Pragma("unroll")                                                \
        for (int g = 0; g < 4; g++)                                      \
            _Pragma("unroll")                                            \
            for (int mi = 0; mi < 2; mi++) {                             \
                hmma(acc[mi][2 * g],     af[mi], bfr[g][0], bfr[g][1]);  \
                hmma(acc[mi][2 * g + 1], af[mi], bfr[g][2], bfr[g][3]);  \
            } }

    LDGB2(0); STSB2(0);
    LDGB2(1); STSB2(1);
    LDGB2(2); STSB2(2);
    FILLA2(0, 0); FILLA2(1, 1); FILLA2(2, 2);

    const int NK = I_ / 32;   // 64
#pragma unroll 1
    for (int kt = 0; kt < NK; ++kt) {
        int st = kt % NSTG;
        cp_wait2();
        __syncthreads();
        int cf = kt + 3;
        bool pf = cf < NK;
        if (pf) { LDGB2(cf); FILLA2(cf, cf % NSTG); } else { cp_commit(); }
        uint32_t so = st * STGB;
        PHASE2(so);
        PHASE2(so + 32);
        if (pf) STSB2(cf % NSTG);
    }

    float bv[8][2];
#pragma unroll
    for (int ni = 0; ni < 8; ni++) {
        int n = n0 + wn * 64 + ni * 8 + tig * 2;
        bv[ni][0] = __ldg(&b2[(size_t)e * H_ + n]);
        bv[ni][1] = __ldg(&b2[(size_t)e * H_ + n + 1]);
    }
#pragma unroll
    for (int mi = 0; mi < 2; mi++) {
#pragma unroll
        for (int rr = 0; rr < 2; rr++) {
            int m = m0 + wm * 32 + mi * 16 + gid + rr * 8;
            if (m >= cnt) continue;
            int tok = g_tok[e * T_ + m];
            int slot = g_slot[e * T_ + m];
            float gt = g_gate[e * T_ + m];
            float* dst = g_ypart + (size_t)(tok * 2 + slot) * H_;
#pragma unroll
            for (int ni = 0; ni < 8; ni++) {
                int n = n0 + wn * 64 + ni * 8 + tig * 2;
                float v0 = (acc[mi][ni][rr * 2 + 0] + bv[ni][0]) * gt;
                float v1 = (acc[mi][ni][rr * 2 + 1] + bv[ni][1]) * gt;
                *reinterpret_cast<float2*>(dst + n) = make_float2(v0, v1);
            }
        }
    }
#undef LDGB2
#undef STSB2
#undef FILLA2
#undef PHASE2
}

// ---------------- deterministic combine ----------------
__global__ void combine_kernel(float* __restrict__ out) {
    int i = blockIdx.x * blockDim.x + threadIdx.x;
    const int HV = H_ / 4;
    int t = i / HV;
    int h = i - t * HV;
    const float4* p0 = reinterpret_cast<const float4*>(g_ypart) + (size_t)(2 * t) * HV + h;
    const float4* p1 = p0 + HV;
    float4 a = *p0, b = *p1;
    reinterpret_cast<float4*>(out)[i] = make_float4(a.x + b.x, a.y + b.y, a.z + b.z, a.w + b.w);
}

// ---------------- launch ----------------
extern "C" void kernel_launch(void* const* d_in, const int* in_sizes, int n_in,
                              void* d_out, int out_size) {
    const float* x      = (const float*)d_in[0];
    const float* logits = (const float*)d_in[1];
    const float* w13    = (const float*)d_in[2];
    const float* w2     = (const float*)d_in[3];
    const float* b13    = (const float*)d_in[4];
    const float* b2     = (const float*)d_in[5];
    float* out = (float*)d_out;

    static int attr_done = 0;
    if (!attr_done) {
        cudaFuncSetAttribute(gemm1_kernel, cudaFuncAttributeMaxDynamicSharedMemorySize, SMEMSZ);
        cudaFuncSetAttribute(gemm2_kernel, cudaFuncAttributeMaxDynamicSharedMemorySize, SMEMSZ);
        attr_done = 1;
    }

    zero_cnt_kernel<<<1, 32>>>();
    presplit_kernel<<<(T_ * H_ / 4) / 256, 256>>>(x);
    router_kernel<<<T_ / 256, 256>>>(logits);

    dim3 g1(I_ / 64, T_ / 64, E_);     // 32 x 16 x 8
    gemm1_kernel<<<g1, 128, SMEMSZ>>>(w13, b13);

    dim3 g2(H_ / 128, T_ / 64, E_);    // 8 x 16 x 8
    gemm2_kernel<<<g2, 128, SMEMSZ>>>(w2, b2);

    combine_kernel<<<(T_ * H_ / 4) / 256, 256>>>(out);
}